// round 1
// baseline (speedup 1.0000x reference)
#include <cuda_runtime.h>
#include <cuda_bf16.h>

#define BB 32
#define CC 64
#define TT 2048
#define KK 16
#define NST 6

#define TILE 128
#define HALO_L 15   // causal window reach (K-1)
#define HALO_R 2    // pooling reach
#define ROW (TILE + HALO_L + HALO_R)   // 145, odd -> conflict-free
#define WPAD 97                        // 96 W entries padded to odd pitch
#define NTHREADS 256

__device__ float g_means[BB * CC];

// ---------------------------------------------------------------------------
// Kernel 1: per-(b,c) mean over T
// ---------------------------------------------------------------------------
__global__ void mean_kernel(const float* __restrict__ x) {
    int row = blockIdx.x;                 // b*C + c
    const float* xr = x + (size_t)row * TT;
    float s = 0.f;
    for (int t = threadIdx.x; t < TT; t += blockDim.x) s += xr[t];
    __shared__ float red[8];
    #pragma unroll
    for (int o = 16; o > 0; o >>= 1) s += __shfl_down_sync(0xffffffffu, s, o);
    if ((threadIdx.x & 31) == 0) red[threadIdx.x >> 5] = s;
    __syncthreads();
    if (threadIdx.x < 8) {
        s = red[threadIdx.x];
        #pragma unroll
        for (int o = 4; o > 0; o >>= 1) s += __shfl_down_sync(0xffu, s, o);
        if (threadIdx.x == 0) g_means[row] = s * (1.0f / TT);
    }
}

// ---------------------------------------------------------------------------
// Kernel 2: fused stats -> grouped 1x1 conv -> softmax-attn -> causal gather
// Grid: B * (T/TILE) CTAs. Block: 256 threads, c = tid&63 fixed per thread
// so the per-channel W row (96 floats) lives in registers.
// ---------------------------------------------------------------------------
extern __shared__ float smem[];

__global__ __launch_bounds__(NTHREADS, 1)
void ddst_main_kernel(const float* __restrict__ x,
                      const float* __restrict__ W,
                      const float* __restrict__ bias,
                      float* __restrict__ out) {
    float* xs = smem;                 // [C][ROW]
    float* ws = smem + CC * ROW;      // [C][WPAD]

    const int ntiles = TT / TILE;
    const int b    = blockIdx.x / ntiles;
    const int tile = blockIdx.x % ntiles;
    const int t0   = tile * TILE;
    const int tid  = threadIdx.x;

    const float* xb = x + (size_t)b * CC * TT;

    // Load x tile with halo (zeros outside [0,T) -- matches zero-padded avg pool)
    for (int idx = tid; idx < CC * ROW; idx += NTHREADS) {
        int c = idx / ROW;
        int j = idx - c * ROW;
        int gt = t0 - HALO_L + j;
        xs[c * ROW + j] = (gt >= 0 && gt < TT) ? xb[(size_t)c * TT + gt] : 0.f;
    }
    // Stage W into shared (coalesced global read, conflict-free reg fill later)
    for (int idx = tid; idx < CC * KK * NST; idx += NTHREADS) {
        int c = idx / (KK * NST);
        int j = idx - c * (KK * NST);
        ws[c * WPAD + j] = W[idx];
    }
    __syncthreads();

    const int c   = tid & (CC - 1);
    const int tl0 = tid >> 6;              // 0..3

    // Per-channel weights into registers (stride 97 -> conflict-free)
    float w[KK * NST];
    #pragma unroll
    for (int j = 0; j < KK * NST; j++) w[j] = ws[c * WPAD + j];
    float bs[KK];
    #pragma unroll
    for (int k = 0; k < KK; k++) bs[k] = __ldg(&bias[c * KK + k]);

    const float gm = g_means[b * CC + c];
    const float* xc = xs + c * ROW + HALO_L;   // xc[tl] == x[b,c,t0+tl]

    for (int tl = tl0; tl < TILE; tl += 4) {
        const int tg = t0 + tl;

        // 5-tap pooling stats
        float s = 0.f, s2 = 0.f;
        float mx = -3.402823466e38f, mn = 3.402823466e38f;
        #pragma unroll
        for (int j = -2; j <= 2; j++) {
            float v = xc[tl + j];
            s  += v;
            s2 += v * v;
            int g = tg + j;
            if (g >= 0 && g < TT) { mx = fmaxf(mx, v); mn = fminf(mn, v); }
        }
        float avg  = s  * 0.2f;
        float avg2 = s2 * 0.2f;
        float var  = fmaxf(avg2 - avg * avg, 1e-6f);
        float sd   = sqrtf(var);
        float xv   = xc[tl];
        float d    = xv - avg;
        float tm   = d * d * d;

        // grouped 1x1 conv: 6 stats -> K dynamic taps
        float kern[KK];
        #pragma unroll
        for (int k = 0; k < KK; k++) {
            const float* wk = w + k * NST;
            float acc = bs[k];
            acc = fmaf(wk[0], xv, acc);
            acc = fmaf(wk[1], gm, acc);
            acc = fmaf(wk[2], sd, acc);
            acc = fmaf(wk[3], tm, acc);
            acc = fmaf(wk[4], mx, acc);
            acc = fmaf(wk[5], mn, acc);
            kern[k] = acc;
        }

        // softmax over |kern|, sign folded into the exp values
        float m = 0.f;
        #pragma unroll
        for (int k = 0; k < KK; k++) m = fmaxf(m, fabsf(kern[k]));
        float sum = 0.f;
        #pragma unroll
        for (int k = 0; k < KK; k++) {
            float a  = fabsf(kern[k]);
            float ev = __expf(a - m);
            sum += ev;
            kern[k] = (kern[k] > 0.f) ? ev : (kern[k] < 0.f ? -ev : 0.f);
        }
        float inv = 1.0f / sum;

        // causal sliding-window gather: x[t + k - (K-1)]
        float acc = 0.f;
        #pragma unroll
        for (int k = 0; k < KK; k++) {
            acc = fmaf(xc[tl + k - (KK - 1)], kern[k], acc);
        }

        // out[b, t, c] -- lanes span consecutive c -> coalesced 128B stores
        out[((size_t)b * TT + tg) * CC + c] = acc * inv;
    }
}

// ---------------------------------------------------------------------------
extern "C" void kernel_launch(void* const* d_in, const int* in_sizes, int n_in,
                              void* d_out, int out_size) {
    const float* x    = (const float*)d_in[0];   // [B, C, T]
    const float* W    = (const float*)d_in[1];   // [C, K, 6]
    const float* bias = (const float*)d_in[2];   // [C, K]
    float* out = (float*)d_out;                  // [B, T, C]

    (void)in_sizes; (void)n_in; (void)out_size;

    mean_kernel<<<BB * CC, 256>>>(x);

    const int smem_bytes = (CC * ROW + CC * WPAD) * (int)sizeof(float);
    cudaFuncSetAttribute(ddst_main_kernel,
                         cudaFuncAttributeMaxDynamicSharedMemorySize, smem_bytes);
    ddst_main_kernel<<<BB * (TT / TILE), NTHREADS, smem_bytes>>>(x, W, bias, out);
}